// round 1
// baseline (speedup 1.0000x reference)
#include <cuda_runtime.h>
#include <math.h>

#define N_TOK  16384
#define DDIM   2048
#define NEXP   64
#define TM     128
#define BK     32
#define KSPLIT 4
#define KC     (DDIM / KSPLIT)   // 512
#define NTILES (KC / BK)         // 16
#define TOPK   8

// 16 MB scratch for K-split partial logits: [KSPLIT][N_TOK][NEXP]
__device__ float g_partial[(size_t)KSPLIT * N_TOK * NEXP];

typedef unsigned long long u64;

__device__ __forceinline__ void ffma2(u64 &d, u64 a, u64 b) {
    asm("fma.rn.f32x2 %0, %1, %2, %0;" : "+l"(d) : "l"(a), "l"(b));
}
__device__ __forceinline__ u64 pack2(float x, float y) {
    u64 r; asm("mov.b64 %0, {%1, %2};" : "=l"(r) : "f"(x), "f"(y)); return r;
}

__device__ __forceinline__ void cp16(float* dst_smem, const float* src) {
    unsigned sa = (unsigned)__cvta_generic_to_shared(dst_smem);
    asm volatile("cp.async.ca.shared.global [%0], [%1], 16;" :: "r"(sa), "l"(src));
}

// Issue one (x,w) tile pair of cp.async 16B copies with XOR chunk swizzle.
__device__ __forceinline__ void issue_tile(const float* __restrict__ xbase,
                                           const float* __restrict__ wbase,
                                           int kof, float* xsb, float* wsb, int tid) {
    #pragma unroll
    for (int i = 0; i < 8; i++) {                    // x tile: 128 rows x 8 chunks
        int lin = i * 128 + tid;
        int r = lin >> 3, cc = lin & 7;
        const float* src = xbase + (size_t)r * DDIM + kof + cc * 4;
        cp16(xsb + r * 32 + ((cc ^ (r & 7)) << 2), src);
    }
    #pragma unroll
    for (int i = 0; i < 4; i++) {                    // w tile: 64 rows x 8 chunks
        int lin = i * 128 + tid;
        int e = lin >> 3, cc = lin & 7;
        const float* src = wbase + (size_t)e * DDIM + kof + cc * 4;
        int col = cc ^ (e & 7) ^ ((e >> 3) & 7);
        cp16(wsb + e * 32 + (col << 2), src);
    }
    asm volatile("cp.async.commit_group;");
}

__global__ void __launch_bounds__(128, 4)
gemm_kernel(const float* __restrict__ x, const float* __restrict__ W) {
    __shared__ float xs[2][TM * BK];     // 2 x 16 KB, swizzled
    __shared__ float ws[2][NEXP * BK];   // 2 x  8 KB, swizzled

    const int tid = threadIdx.x;
    const int t0  = blockIdx.x * TM;
    const int kz  = blockIdx.y;
    const int k0  = kz * KC;

    // Warp-internal layout: 8 distinct token-groups x 4 expert-groups per warp
    const int g  = (tid & 7) | (((tid >> 5) & 1) << 3);        // 0..15 (token group)
    const int eg = ((tid >> 3) & 3) | (((tid >> 6) & 1) << 2); // 0..7  (expert group)

    u64 acc[8][4];   // [token i][expert pair jp]: packed (e_even, e_odd) f32x2
    #pragma unroll
    for (int i = 0; i < 8; i++)
        #pragma unroll
        for (int jp = 0; jp < 4; jp++) acc[i][jp] = 0ull;

    const float* xbase = x + (size_t)t0 * DDIM + k0;
    const float* wbase = W + k0;

    issue_tile(xbase, wbase, 0, xs[0], ws[0], tid);

    for (int tile = 0; tile < NTILES; ++tile) {
        const int buf = tile & 1;
        if (tile + 1 < NTILES) {
            issue_tile(xbase, wbase, (tile + 1) * BK, xs[buf ^ 1], ws[buf ^ 1], tid);
            asm volatile("cp.async.wait_group 1;");
        } else {
            asm volatile("cp.async.wait_group 0;");
        }
        __syncthreads();

        #pragma unroll
        for (int kc = 0; kc < 8; ++kc) {         // 8 chunks of 4 k each
            // b: 8 experts x 4 k values  (broadcast reads, conflict-free)
            float bf[8][4];
            #pragma unroll
            for (int j = 0; j < 8; j++) {
                int e = eg * 8 + j;
                int col = kc ^ (e & 7) ^ ((e >> 3) & 7);
                float4 v = *(const float4*)&ws[buf][e * 32 + (col << 2)];
                bf[j][0] = v.x; bf[j][1] = v.y; bf[j][2] = v.z; bf[j][3] = v.w;
            }
            // Pre-pack expert pairs per k
            u64 bp[4][4];
            #pragma unroll
            for (int jp = 0; jp < 4; jp++)
                #pragma unroll
                for (int q = 0; q < 4; q++)
                    bp[jp][q] = pack2(bf[2 * jp][q], bf[2 * jp + 1][q]);

            #pragma unroll
            for (int i = 0; i < 8; i++) {
                int t = g + 16 * i;
                float4 a = *(const float4*)&xs[buf][t * 32 + ((kc ^ (t & 7)) << 2)];
                float af[4] = {a.x, a.y, a.z, a.w};
                #pragma unroll
                for (int q = 0; q < 4; q++) {
                    u64 ad = pack2(af[q], af[q]);
                    #pragma unroll
                    for (int jp = 0; jp < 4; jp++)
                        ffma2(acc[i][jp], ad, bp[jp][q]);
                }
            }
        }
        __syncthreads();
    }

    // Epilogue: write packed pairs to the partial buffer
    float* outp = g_partial + ((size_t)kz * N_TOK + t0) * NEXP;
    #pragma unroll
    for (int i = 0; i < 8; i++) {
        int t = g + 16 * i;
        #pragma unroll
        for (int jp = 0; jp < 4; jp++)
            *(u64*)(outp + (size_t)t * NEXP + eg * 8 + 2 * jp) = acc[i][jp];
    }
}

__global__ void __launch_bounds__(128)
topk_kernel(const float* __restrict__ bias, float* __restrict__ out) {
    const int t = blockIdx.x * blockDim.x + threadIdx.x;
    if (t >= N_TOK) return;
    const float* p = g_partial + (size_t)t * NEXP;
    const size_t SPLIT = (size_t)N_TOK * NEXP;

    float val[TOPK]; int idx[TOPK];
    #pragma unroll
    for (int r = 0; r < TOPK; r++) { val[r] = -INFINITY; idx[r] = 0; }

    for (int c = 0; c < NEXP / 4; c++) {
        float4 v0 = *(const float4*)(p + c * 4);
        float4 v1 = *(const float4*)(p + SPLIT + c * 4);
        float4 v2 = *(const float4*)(p + 2 * SPLIT + c * 4);
        float4 v3 = *(const float4*)(p + 3 * SPLIT + c * 4);
        float s[4] = {v0.x + v1.x + v2.x + v3.x,
                      v0.y + v1.y + v2.y + v3.y,
                      v0.z + v1.z + v2.z + v3.z,
                      v0.w + v1.w + v2.w + v3.w};
        #pragma unroll
        for (int j = 0; j < 4; j++) {
            int e = c * 4 + j;
            float z = s[j] + bias[e];
            float sc = 1.0f / (1.0f + expf(-z));
            // Stable descending insertion: strict > keeps earlier index on ties
            if (sc > val[TOPK - 1]) {
                int pos = TOPK - 1;
                while (pos > 0 && sc > val[pos - 1]) {
                    val[pos] = val[pos - 1]; idx[pos] = idx[pos - 1]; pos--;
                }
                val[pos] = sc; idx[pos] = e;
            }
        }
    }

    // Output layout: [all top_w][all top_idx as float], flattened [B,S,8]
    #pragma unroll
    for (int r = 0; r < TOPK; r++) {
        out[(size_t)t * TOPK + r] = val[r];
        out[(size_t)N_TOK * TOPK + (size_t)t * TOPK + r] = (float)idx[r];
    }
}

extern "C" void kernel_launch(void* const* d_in, const int* in_sizes, int n_in,
                              void* d_out, int out_size) {
    const float* x = (const float*)d_in[0];
    const float* W = (const float*)d_in[1];
    const float* b = (const float*)d_in[2];
    float* out = (float*)d_out;

    dim3 grid(N_TOK / TM, KSPLIT);
    gemm_kernel<<<grid, 128>>>(x, W);
    topk_kernel<<<N_TOK / 128, 128>>>(b, out);
}

// round 2
// speedup vs baseline: 1.0306x; 1.0306x over previous
#include <cuda_runtime.h>
#include <math.h>

#define N_TOK   16384
#define DDIM    2048
#define NEXP    64
#define TM      128
#define BK      32
#define NTILES  (DDIM / BK)     // 64
#define TOPK    8
#define THREADS 256
#define LPAD    66              // padded logits row (words)

// W transposed: [k][e], 512 KB
__device__ float g_Wt[DDIM * NEXP];

typedef unsigned long long u64;

__device__ __forceinline__ void ffma2(u64 &d, u64 a, u64 b) {
    asm("fma.rn.f32x2 %0, %1, %2, %0;" : "+l"(d) : "l"(a), "l"(b));
}
__device__ __forceinline__ u64 pack2(float x, float y) {
    u64 r; asm("mov.b64 %0, {%1, %2};" : "=l"(r) : "f"(x), "f"(y)); return r;
}
__device__ __forceinline__ void cp16(float* dst, const float* src) {
    unsigned sa = (unsigned)__cvta_generic_to_shared(dst);
    asm volatile("cp.async.ca.shared.global [%0], [%1], 16;" :: "r"(sa), "l"(src));
}

__global__ void __launch_bounds__(256) wt_kernel(const float* __restrict__ W) {
    int n = blockIdx.x * 256 + threadIdx.x;   // n = k*64 + e
    int k = n >> 6, e = n & 63;
    g_Wt[n] = W[(size_t)e * DDIM + k];
}

// x tile (swizzled rows) + transposed w tile, double buffered
__device__ __forceinline__ void issue_tile(const float* __restrict__ xbase, int tile,
                                           float* xsb, float* wsb, int tid) {
    #pragma unroll
    for (int it = 0; it < 4; it++) {               // x: 128 rows x 8 chunks of 16B
        int lin = it * THREADS + tid;
        int r = lin >> 3, cc = lin & 7;
        cp16(xsb + r * BK + ((cc ^ (r & 7)) << 2),
             xbase + (size_t)r * DDIM + tile * BK + cc * 4);
    }
    const float* wsrc = g_Wt + (size_t)tile * BK * NEXP;   // contiguous 8 KB
    #pragma unroll
    for (int it = 0; it < 2; it++) {
        int j = it * THREADS + tid;
        cp16(wsb + j * 4, wsrc + j * 4);
    }
    asm volatile("cp.async.commit_group;");
}

__global__ void __launch_bounds__(THREADS, 1)
router_kernel(const float* __restrict__ x, const float* __restrict__ bias,
              float* __restrict__ out) {
    __shared__ float smem[2 * TM * BK + 2 * BK * NEXP];   // 48 KB
    float* xsb[2] = { smem, smem + TM * BK };
    float* wsb[2] = { smem + 2 * TM * BK, smem + 2 * TM * BK + BK * NEXP };

    const int tid = threadIdx.x;
    const int t0  = blockIdx.x * TM;
    const int g   = tid >> 3;     // token group 0..31 -> tokens g + 32*i
    const int eg  = tid & 7;      // expert group 0..7 -> experts eg*8 .. eg*8+7

    u64 acc[4][4];                // [token i][expert-pair jp]; pairs (2e, 2e+1)
    #pragma unroll
    for (int i = 0; i < 4; i++)
        #pragma unroll
        for (int jp = 0; jp < 4; jp++) acc[i][jp] = 0ull;

    const float* xbase = x + (size_t)t0 * DDIM;

    issue_tile(xbase, 0, xsb[0], wsb[0], tid);

    for (int tile = 0; tile < NTILES; ++tile) {
        const int buf = tile & 1;
        if (tile + 1 < NTILES) {
            issue_tile(xbase, tile + 1, xsb[buf ^ 1], wsb[buf ^ 1], tid);
            asm volatile("cp.async.wait_group 1;");
        } else {
            asm volatile("cp.async.wait_group 0;");
        }
        __syncthreads();

        const float* xb = xsb[buf];
        const float* wb = wsb[buf];
        #pragma unroll
        for (int kc = 0; kc < 8; ++kc) {            // 8 chunks of 4 k
            float4 a[4];
            #pragma unroll
            for (int i = 0; i < 4; i++) {
                int t = g + 32 * i;
                a[i] = *(const float4*)&xb[t * BK + ((kc ^ (g & 7)) << 2)];
            }
            #pragma unroll
            for (int q = 0; q < 4; q++) {
                int k = kc * 4 + q;
                // two LDS.128 -> 4 pre-paired f32x2 B operands (experts eg*8..eg*8+7)
                ulonglong2 bA = *(const ulonglong2*)&wb[k * NEXP + eg * 8];
                ulonglong2 bB = *(const ulonglong2*)&wb[k * NEXP + eg * 8 + 4];
                #pragma unroll
                for (int i = 0; i < 4; i++) {
                    float av = (q == 0) ? a[i].x : (q == 1) ? a[i].y
                             : (q == 2) ? a[i].z : a[i].w;
                    u64 ad = pack2(av, av);
                    ffma2(acc[i][0], ad, bA.x);
                    ffma2(acc[i][1], ad, bA.y);
                    ffma2(acc[i][2], ad, bB.x);
                    ffma2(acc[i][3], ad, bB.y);
                }
            }
        }
        __syncthreads();
    }

    // ---- epilogue: dump logits to smem, then per-token sigmoid + top-8 ----
    float* logits = smem;                       // [TM][LPAD], 8448 floats < 12288
    #pragma unroll
    for (int i = 0; i < 4; i++) {
        int t = g + 32 * i;
        #pragma unroll
        for (int jp = 0; jp < 4; jp++)
            *(u64*)&logits[t * LPAD + eg * 8 + 2 * jp] = acc[i][jp];
    }
    __syncthreads();

    if (tid < TM) {
        const float* p = &logits[tid * LPAD];
        float val[TOPK]; int idx[TOPK];
        #pragma unroll
        for (int r = 0; r < TOPK; r++) { val[r] = -INFINITY; idx[r] = 0; }

        for (int e = 0; e < NEXP; e++) {
            float z = p[e] + __ldg(&bias[e]);
            float sc = 1.0f / (1.0f + expf(-z));
            if (sc > val[TOPK - 1]) {            // strict >: first index wins ties
                int pos = TOPK - 1;
                while (pos > 0 && sc > val[pos - 1]) {
                    val[pos] = val[pos - 1]; idx[pos] = idx[pos - 1]; pos--;
                }
                val[pos] = sc; idx[pos] = e;
            }
        }

        int t = t0 + tid;
        #pragma unroll
        for (int r = 0; r < TOPK; r++) {
            out[(size_t)t * TOPK + r] = val[r];
            out[(size_t)N_TOK * TOPK + (size_t)t * TOPK + r] = (float)idx[r];
        }
    }
}

extern "C" void kernel_launch(void* const* d_in, const int* in_sizes, int n_in,
                              void* d_out, int out_size) {
    const float* x = (const float*)d_in[0];
    const float* W = (const float*)d_in[1];
    const float* b = (const float*)d_in[2];
    float* out = (float*)d_out;

    wt_kernel<<<(DDIM * NEXP) / 256, 256>>>(W);
    router_kernel<<<N_TOK / TM, THREADS>>>(x, b, out);
}

// round 4
// speedup vs baseline: 1.6830x; 1.6329x over previous
#include <cuda_runtime.h>
#include <cuda_fp16.h>
#include <math.h>
#include <stdint.h>

#define N_TOK   16384
#define DDIM    2048
#define NEXP    64
#define TM      128
#define NKS     (DDIM / 16)     // 128 k-steps of 16
#define TOPK    8
#define THREADS 256
#define LPAD    66

#define XS        16.0f          // 2^4
#define WSC       1024.0f        // 2^10
#define SCALE_INV 6.103515625e-05f  // 2^-14

// B in HMMA-fragment order: [ks][(nb*2+plane)][lane][reg] as u32; 512 KB
__device__ uint32_t g_Bfrag[NKS * 1024];

static __device__ __forceinline__ uint32_t h2u(__half2 h) {
    return reinterpret_cast<uint32_t&>(h);
}

static __device__ __forceinline__ void hmma(float* c, const uint32_t* a,
                                            uint32_t b0, uint32_t b1) {
    asm("mma.sync.aligned.m16n8k16.row.col.f32.f16.f16.f32 "
        "{%0,%1,%2,%3}, {%4,%5,%6,%7}, {%8,%9}, {%0,%1,%2,%3};"
        : "+f"(c[0]), "+f"(c[1]), "+f"(c[2]), "+f"(c[3])
        : "r"(a[0]), "r"(a[1]), "r"(a[2]), "r"(a[3]), "r"(b0), "r"(b1));
}

static __device__ __forceinline__ void cp16(void* smem_dst, const void* gsrc) {
    uint32_t sa;
    asm("{ .reg .u64 t; cvta.to.shared.u64 t, %1; cvt.u32.u64 %0, t; }"
        : "=r"(sa) : "l"(smem_dst));
    asm volatile("cp.async.ca.shared.global [%0], [%1], 16;" :: "r"(sa), "l"(gsrc));
}

// 4 float2 (scaled) -> 4 hi u32 + 4 lo u32 (residual) half2 frags
static __device__ __forceinline__ void cvt4(const float2* p, uint32_t* hi, uint32_t* lo) {
    #pragma unroll
    for (int i = 0; i < 4; i++) {
        float v0 = p[i].x * XS, v1 = p[i].y * XS;
        __half2 h = __floats2half2_rn(v0, v1);
        float2 hf = __half22float2(h);
        __half2 r = __floats2half2_rn(v0 - hf.x, v1 - hf.y);
        hi[i] = h2u(h); lo[i] = h2u(r);
    }
}

// ---- prep: W -> fp16 hi/lo planes in HMMA B-fragment order ----
__global__ void __launch_bounds__(256) wprep_kernel(const float* __restrict__ W) {
    int idx = blockIdx.x * 256 + threadIdx.x;        // 65536 (ks, nb, lane, reg)
    int reg = idx & 1, l = (idx >> 1) & 31, nb = (idx >> 6) & 7, ks = idx >> 9;
    int n = nb * 8 + (l >> 2);
    int k = ks * 16 + (l & 3) * 2 + reg * 8;
    float2 w = *(const float2*)(W + (size_t)n * DDIM + k);
    float v0 = w.x * WSC, v1 = w.y * WSC;
    __half2 h = __floats2half2_rn(v0, v1);
    float2 hf = __half22float2(h);
    __half2 r = __floats2half2_rn(v0 - hf.x, v1 - hf.y);
    int base = ks * 1024 + nb * 128 + l * 2 + reg;   // plane stride = 64 u32
    g_Bfrag[base]      = h2u(h);                     // hi plane
    g_Bfrag[base + 64] = h2u(r);                     // lo plane
}

// ---- fused router ----
__global__ void __launch_bounds__(THREADS)
router_kernel(const float* __restrict__ x, const float* __restrict__ bias,
              float* __restrict__ out) {
    __shared__ uint4 bsm[2][256];          // 2 x 4KB B-fragment stages
    __shared__ float logits[TM][LPAD];     // 33.8 KB

    const int tid = threadIdx.x;
    const int wid = tid >> 5, l = tid & 31;
    const int g = l >> 2, kp = (l & 3) * 2;
    const int t0 = blockIdx.x * TM;

    const float* xr0 = x + (size_t)(t0 + wid * 16 + g) * DDIM;
    const float* xr1 = xr0 + 8 * DDIM;

    float acc[8][4];
    #pragma unroll
    for (int nb = 0; nb < 8; nb++)
        #pragma unroll
        for (int c = 0; c < 4; c++) acc[nb][c] = 0.0f;

    // prologue: B ks=0 -> stage 0; A raw for ks=0
    cp16(&bsm[0][tid & 255], g_Bfrag + tid * 4);
    asm volatile("cp.async.commit_group;");

    float2 raw[4];
    raw[0] = *(const float2*)(xr0 + kp);
    raw[1] = *(const float2*)(xr1 + kp);
    raw[2] = *(const float2*)(xr0 + kp + 8);
    raw[3] = *(const float2*)(xr1 + kp + 8);
    uint32_t ahi[4], alo[4];
    cvt4(raw, ahi, alo);

    for (int ks = 0; ks < NKS; ks++) {
        const int buf = ks & 1;
        __syncthreads();   // everyone done reading bsm[buf^1] (iter ks-1)
        if (ks + 1 < NKS)
            cp16(&bsm[buf ^ 1][tid], g_Bfrag + (ks + 1) * 1024 + tid * 4);
        asm volatile("cp.async.commit_group;");
        asm volatile("cp.async.wait_group 1;");
        __syncthreads();   // stage `buf` (group ks) visible to all

        // prefetch A raw for next k-step
        int kn = (ks + 1 < NKS) ? (ks + 1) * 16 : ks * 16;
        raw[0] = *(const float2*)(xr0 + kn + kp);
        raw[1] = *(const float2*)(xr1 + kn + kp);
        raw[2] = *(const float2*)(xr0 + kn + kp + 8);
        raw[3] = *(const float2*)(xr1 + kn + kp + 8);

        const uint32_t* bp = (const uint32_t*)&bsm[buf][0];
        #pragma unroll
        for (int nb = 0; nb < 8; nb++) {
            uint2 bhi = *(const uint2*)(bp + nb * 128 + l * 2);
            uint2 blo = *(const uint2*)(bp + nb * 128 + 64 + l * 2);
            hmma(acc[nb], ahi, bhi.x, bhi.y);
            hmma(acc[nb], ahi, blo.x, blo.y);
            hmma(acc[nb], alo, bhi.x, bhi.y);
        }

        cvt4(raw, ahi, alo);
    }

    // ---- dump logits, then per-token sigmoid + top-8 ----
    const int r0 = wid * 16 + g;
    #pragma unroll
    for (int nb = 0; nb < 8; nb++) {
        int c0 = nb * 8 + kp;
        *(float2*)&logits[r0][c0]     = make_float2(acc[nb][0], acc[nb][1]);
        *(float2*)&logits[r0 + 8][c0] = make_float2(acc[nb][2], acc[nb][3]);
    }
    __syncthreads();

    if (tid < TM) {
        const float* p = &logits[tid][0];
        float val[TOPK]; int idx[TOPK];
        #pragma unroll
        for (int r = 0; r < TOPK; r++) { val[r] = -INFINITY; idx[r] = 0; }

        for (int e = 0; e < NEXP; e++) {
            float z = p[e] * SCALE_INV + __ldg(&bias[e]);
            float sc = 1.0f / (1.0f + expf(-z));
            if (sc > val[TOPK - 1]) {            // strict >: earliest index wins ties
                int pos = TOPK - 1;
                while (pos > 0 && sc > val[pos - 1]) {
                    val[pos] = val[pos - 1]; idx[pos] = idx[pos - 1]; pos--;
                }
                val[pos] = sc; idx[pos] = e;
            }
        }

        int t = t0 + tid;
        #pragma unroll
        for (int r = 0; r < TOPK; r++) {
            out[(size_t)t * TOPK + r] = val[r];
            out[(size_t)N_TOK * TOPK + (size_t)t * TOPK + r] = (float)idx[r];
        }
    }
}

extern "C" void kernel_launch(void* const* d_in, const int* in_sizes, int n_in,
                              void* d_out, int out_size) {
    const float* x = (const float*)d_in[0];
    const float* W = (const float*)d_in[1];
    const float* b = (const float*)d_in[2];
    float* out = (float*)d_out;

    wprep_kernel<<<NKS * 1024 / 2 / 256, 256>>>(W);
    router_kernel<<<N_TOK / TM, THREADS>>>(x, b, out);
}

// round 5
// speedup vs baseline: 2.6983x; 1.6033x over previous
#include <cuda_runtime.h>
#include <cuda_fp16.h>
#include <math.h>
#include <stdint.h>

#define N_TOK   16384
#define DDIM    2048
#define NEXP    64
#define TM      128
#define NKS     (DDIM / 16)     // 128 k-steps of 16
#define NCH     (DDIM / 64)     // 32 chunks of 64 k (4 k-steps)
#define TOPK    8
#define THREADS 256
#define LPAD    66

#define XS        16.0f             // 2^4
#define WSC       1024.0f           // 2^10
#define SCALE_INV 6.103515625e-05f  // 2^-14

// B in HMMA-fragment order: [ks][nb*128 + plane*64 + lane*2 + reg]; 512 KB
__device__ uint32_t g_Bfrag[NKS * 1024];

static __device__ __forceinline__ uint32_t h2u(__half2 h) {
    return reinterpret_cast<uint32_t&>(h);
}

static __device__ __forceinline__ void hmma(float* c, const uint32_t* a,
                                            uint32_t b0, uint32_t b1) {
    asm("mma.sync.aligned.m16n8k16.row.col.f32.f16.f16.f32 "
        "{%0,%1,%2,%3}, {%4,%5,%6,%7}, {%8,%9}, {%0,%1,%2,%3};"
        : "+f"(c[0]), "+f"(c[1]), "+f"(c[2]), "+f"(c[3])
        : "r"(a[0]), "r"(a[1]), "r"(a[2]), "r"(a[3]), "r"(b0), "r"(b1));
}

static __device__ __forceinline__ void cp16(void* smem_dst, const void* gsrc) {
    uint32_t sa;
    asm("{ .reg .u64 t; cvta.to.shared.u64 t, %1; cvt.u32.u64 %0, t; }"
        : "=r"(sa) : "l"(smem_dst));
    asm volatile("cp.async.ca.shared.global [%0], [%1], 16;" :: "r"(sa), "l"(gsrc));
}

// 4 float2 (scaled) -> 4 hi + 4 lo half2 frags
static __device__ __forceinline__ void cvt4(const float2* p, uint32_t* hi, uint32_t* lo) {
    #pragma unroll
    for (int i = 0; i < 4; i++) {
        float v0 = p[i].x * XS, v1 = p[i].y * XS;
        __half2 h = __floats2half2_rn(v0, v1);
        float2 hf = __half22float2(h);
        __half2 r = __floats2half2_rn(v0 - hf.x, v1 - hf.y);
        hi[i] = h2u(h); lo[i] = h2u(r);
    }
}

// ---- prep: W -> fp16 hi/lo planes in HMMA B-fragment order ----
__global__ void __launch_bounds__(256) wprep_kernel(const float* __restrict__ W) {
    int idx = blockIdx.x * 256 + threadIdx.x;        // (ks, nb, lane, reg)
    int reg = idx & 1, l = (idx >> 1) & 31, nb = (idx >> 6) & 7, ks = idx >> 9;
    int n = nb * 8 + (l >> 2);
    int k = ks * 16 + (l & 3) * 2 + reg * 8;
    float2 w = *(const float2*)(W + (size_t)n * DDIM + k);
    float v0 = w.x * WSC, v1 = w.y * WSC;
    __half2 h = __floats2half2_rn(v0, v1);
    float2 hf = __half22float2(h);
    __half2 r = __floats2half2_rn(v0 - hf.x, v1 - hf.y);
    int base = ks * 1024 + nb * 128 + l * 2 + reg;
    g_Bfrag[base]      = h2u(h);
    g_Bfrag[base + 64] = h2u(r);
}

union SmemU {
    uint32_t b[2][4096];         // 2 x 16 KB B stages (4 k-steps each)
    float logits[TM][LPAD];      // 33.8 KB epilogue buffer
};

static __device__ __forceinline__ void mma_step(float acc[8][4],
                                                const uint32_t* ahi, const uint32_t* alo,
                                                const uint32_t* bpks, int l) {
    #pragma unroll
    for (int nb = 0; nb < 8; nb++) {
        uint2 bhi = *(const uint2*)(bpks + nb * 128 + l * 2);
        uint2 blo = *(const uint2*)(bpks + nb * 128 + 64 + l * 2);
        hmma(acc[nb], ahi, bhi.x, bhi.y);
        hmma(acc[nb], ahi, blo.x, blo.y);
        hmma(acc[nb], alo, bhi.x, bhi.y);
    }
}

// ---- fused router ----
__global__ void __launch_bounds__(THREADS)
router_kernel(const float* __restrict__ x, const float* __restrict__ bias,
              float* __restrict__ out) {
    __shared__ SmemU sm;

    const int tid = threadIdx.x;
    const int wid = tid >> 5, l = tid & 31;
    const int g = l >> 2, kp = (l & 3) * 2;
    const int t0 = blockIdx.x * TM;

    const float* xr0 = x + (size_t)(t0 + wid * 16 + g) * DDIM;
    const float* xr1 = xr0 + 8 * DDIM;

    float acc[8][4];
    #pragma unroll
    for (int nb = 0; nb < 8; nb++)
        #pragma unroll
        for (int c = 0; c < 4; c++) acc[nb][c] = 0.0f;

    // prologue: B chunk 0 -> stage 0
    {
        const uint4* src = (const uint4*)g_Bfrag;
        #pragma unroll
        for (int i = 0; i < 4; i++)
            cp16(&((uint4*)sm.b[0])[tid + i * 256], src + tid + i * 256);
        asm volatile("cp.async.commit_group;");
    }

    // A raw for chunk 0 (16 float2 per lane: 4 k-steps x 4 frag halves)
    float2 raw[16];
    #pragma unroll
    for (int ks = 0; ks < 4; ks++) {
        int k = ks * 16 + kp;
        raw[ks * 4 + 0] = *(const float2*)(xr0 + k);
        raw[ks * 4 + 1] = *(const float2*)(xr1 + k);
        raw[ks * 4 + 2] = *(const float2*)(xr0 + k + 8);
        raw[ks * 4 + 3] = *(const float2*)(xr1 + k + 8);
    }

    for (int c = 0; c < NCH; c++) {
        const int buf = c & 1;
        __syncthreads();                      // all warps done reading stage buf^1
        if (c + 1 < NCH) {
            const uint4* src = (const uint4*)(g_Bfrag + (c + 1) * 4096);
            #pragma unroll
            for (int i = 0; i < 4; i++)
                cp16(&((uint4*)sm.b[buf ^ 1])[tid + i * 256], src + tid + i * 256);
            asm volatile("cp.async.commit_group;");
            asm volatile("cp.async.wait_group 1;");
        } else {
            asm volatile("cp.async.wait_group 0;");
        }
        __syncthreads();                      // stage buf visible to all

        const uint32_t* bp = sm.b[buf];
        const int kn = ((c + 1 < NCH) ? (c + 1) : c) * 64 + kp;

        uint32_t ahi0[4], alo0[4], ahi1[4], alo1[4];

        // ---- half 1: ks 0,1 ----
        cvt4(&raw[0], ahi0, alo0);
        cvt4(&raw[4], ahi1, alo1);
        #pragma unroll
        for (int ks = 0; ks < 2; ks++) {      // prefetch bank0 for next chunk
            int k = kn + ks * 16;
            raw[ks * 4 + 0] = *(const float2*)(xr0 + k);
            raw[ks * 4 + 1] = *(const float2*)(xr1 + k);
            raw[ks * 4 + 2] = *(const float2*)(xr0 + k + 8);
            raw[ks * 4 + 3] = *(const float2*)(xr1 + k + 8);
        }
        mma_step(acc, ahi0, alo0, bp, l);
        mma_step(acc, ahi1, alo1, bp + 1024, l);

        // ---- half 2: ks 2,3 ----
        cvt4(&raw[8],  ahi0, alo0);
        cvt4(&raw[12], ahi1, alo1);
        #pragma unroll
        for (int ks = 2; ks < 4; ks++) {      // prefetch bank1 for next chunk
            int k = kn + ks * 16;
            raw[ks * 4 + 0] = *(const float2*)(xr0 + k);
            raw[ks * 4 + 1] = *(const float2*)(xr1 + k);
            raw[ks * 4 + 2] = *(const float2*)(xr0 + k + 8);
            raw[ks * 4 + 3] = *(const float2*)(xr1 + k + 8);
        }
        mma_step(acc, ahi0, alo0, bp + 2048, l);
        mma_step(acc, ahi1, alo1, bp + 3072, l);
    }

    // ---- dump logits, then per-token sigmoid + top-8 ----
    __syncthreads();
    const int r0 = wid * 16 + g;
    #pragma unroll
    for (int nb = 0; nb < 8; nb++) {
        int c0 = nb * 8 + kp;
        *(float2*)&sm.logits[r0][c0]     = make_float2(acc[nb][0], acc[nb][1]);
        *(float2*)&sm.logits[r0 + 8][c0] = make_float2(acc[nb][2], acc[nb][3]);
    }
    __syncthreads();

    if (tid < TM) {
        const float* p = &sm.logits[tid][0];
        float val[TOPK]; int idx[TOPK];
        #pragma unroll
        for (int r = 0; r < TOPK; r++) { val[r] = -INFINITY; idx[r] = 0; }

        for (int e = 0; e < NEXP; e++) {
            float z = p[e] * SCALE_INV + __ldg(&bias[e]);
            float sc = 1.0f / (1.0f + expf(-z));
            if (sc > val[TOPK - 1]) {            // strict >: earliest index wins ties
                int pos = TOPK - 1;
                while (pos > 0 && sc > val[pos - 1]) {
                    val[pos] = val[pos - 1]; idx[pos] = idx[pos - 1]; pos--;
                }
                val[pos] = sc; idx[pos] = e;
            }
        }

        int t = t0 + tid;
        #pragma unroll
        for (int r = 0; r < TOPK; r++) {
            out[(size_t)t * TOPK + r] = val[r];
            out[(size_t)N_TOK * TOPK + (size_t)t * TOPK + r] = (float)idx[r];
        }
    }
}

extern "C" void kernel_launch(void* const* d_in, const int* in_sizes, int n_in,
                              void* d_out, int out_size) {
    const float* x = (const float*)d_in[0];
    const float* W = (const float*)d_in[1];
    const float* b = (const float*)d_in[2];
    float* out = (float*)d_out;

    wprep_kernel<<<NKS * 1024 / 2 / 256, 256>>>(W);
    router_kernel<<<N_TOK / TM, THREADS>>>(x, b, out);
}